// round 6
// baseline (speedup 1.0000x reference)
#include <cuda_runtime.h>
#include <math.h>
#include <stdint.h>

// Problem constants
#define BB    8
#define CC    128
#define NN    65536
#define NOBJ  64

#define PBLK     512               // points per stage-1 block (chunk)
#define HT       32                // points per half-tile
#define NHT      (PBLK / HT)       // 16 half-tiles
#define TCOLS    64                // tile columns (2 half-tiles resident)
#define THREADS1 512               // 16 warps; warp w owns segs 4w..4w+3
#define NWARP    16
#define NCHUNK   (NN / PBLK)       // 128
#define NCID     (BB * NCHUNK)     // 1024 chunks total
#define NBUCK    (NWARP * NHT)     // 256 buckets per chunk

// Scratch (static device arrays: allowed).
// __align__(16): these are accessed through uint32_t*/vector casts; the
// natural 2-byte alignment of u16 arrays caused the Round-5 misaligned trap.
__device__ float g_partial[(size_t)NCID * NOBJ * CC];                  // 32 MB
__device__ __align__(16) unsigned short g_entries[NCID * PBLK];        // 1 MB
__device__ __align__(16) unsigned short g_pref[NCID * (NBUCK + 1)];    // 514 KB

// ---- cp.async helpers ------------------------------------------------------
__device__ __forceinline__ void cp_async16(uint32_t dst, const void* src) {
    asm volatile("cp.async.cg.shared.global [%0], [%1], 16;\n" :: "r"(dst), "l"(src));
}
__device__ __forceinline__ void cp_commit() { asm volatile("cp.async.commit_group;\n"); }
template <int N> __device__ __forceinline__ void cp_wait() {
    asm volatile("cp.async.wait_group %0;\n" :: "n"(N));
}

// ---------------------------------------------------------------------------
// Prep: dtype-probe box_idx (int32 vs int64), then counting-sort each chunk's
// 512 points into 256 buckets keyed (owner_warp = s>>2, half_tile = pt>>5).
// Order within a bucket is irrelevant (max is commutative) so an atomic rank
// suffices. Entry = pt (9 bits) | (s&3)<<9. Bucket contents are deterministic;
// intra-bucket order varies but max() erases it.
// ---------------------------------------------------------------------------
__global__ void prep_sort(const int* __restrict__ idx32) {
    __shared__ int ok;
    __shared__ int hist[NBUCK];
    __shared__ int wsum[8];
    __shared__ int pos[NBUCK];

    const int tid = threadIdx.x;          // 256
    const int cid = blockIdx.x;           // 1024 chunks
    if (tid == 0) ok = 1;
    hist[tid] = 0;
    __syncthreads();
    {   // int64 in [0,64) -> int32 view [v,0,v,0,...]; random int32 can't
        // keep all 256 odd words zero -> unambiguous.
        int lo = idx32[2 * tid];
        int hi = idx32[2 * tid + 1];
        if (hi != 0 || lo < 0 || lo >= NOBJ) atomicAnd(&ok, 0);
    }
    __syncthreads();
    const int stride = ok ? 2 : 1;

    const int p0 = tid, p1 = tid + 256;   // two points per thread
    int s0 = idx32[(size_t)(cid * PBLK + p0) * stride];
    int s1 = idx32[(size_t)(cid * PBLK + p1) * stride];
    int b0 = (s0 >> 2) * NHT + (p0 >> 5);
    int b1 = (s1 >> 2) * NHT + (p1 >> 5);
    atomicAdd(&hist[b0], 1);
    atomicAdd(&hist[b1], 1);
    __syncthreads();

    // exclusive scan over hist[256]
    const int lane = tid & 31, wid = tid >> 5;
    int v = hist[tid];
    int inc = v;
    #pragma unroll
    for (int d = 1; d < 32; d <<= 1) {
        int t = __shfl_up_sync(0xffffffffu, inc, d);
        if (lane >= d) inc += t;
    }
    if (lane == 31) wsum[wid] = inc;
    __syncthreads();
    if (tid == 0) {
        int run = 0;
        #pragma unroll
        for (int i = 0; i < 8; ++i) { int t = wsum[i]; wsum[i] = run; run += t; }
    }
    __syncthreads();
    int exc = inc - v + wsum[wid];
    pos[tid] = exc;
    g_pref[cid * (NBUCK + 1) + tid] = (unsigned short)exc;
    if (tid == 0) g_pref[cid * (NBUCK + 1) + NBUCK] = (unsigned short)PBLK;
    __syncthreads();

    int r0 = atomicAdd(&pos[b0], 1);
    g_entries[cid * PBLK + r0] = (unsigned short)(p0 | ((s0 & 3) << 9));
    int r1 = atomicAdd(&pos[b1], 1);
    g_entries[cid * PBLK + r1] = (unsigned short)(p1 | ((s1 & 3) << 9));
}

// ---------------------------------------------------------------------------
// Stage 1: register-accumulator segment max.
//   Warp w owns segments 4w..4w+3; lane l owns channels {l, l+32, l+64, l+96}.
//   Acc = 16 registers per thread, updated by predicated FMAX (no smem RMW,
//   no atomics, no alias hazards).
//   Tile: channel-major [128][64 cols], 16-granule XOR swizzle g^(c&15).
//   XOR by a constant is a bijection -> each logical half-tile occupies a
//   fixed, disjoint physical granule set per row: half-buffer refills never
//   clobber the half in flight. cp.async writes stay 4-wavefront; point-gather
//   reads are 4-way bank conflicted (acceptable; see cost model).
//   Drain: wait_group 1 except final iteration (wait_group 0) — Round-3 rule.
// ---------------------------------------------------------------------------
__global__ __launch_bounds__(THREADS1) void seg_max_stage1(
    const float* __restrict__ feat)
{
    __shared__ float          tile[CC * TCOLS];   // 32 KB
    __shared__ unsigned short Psm[NBUCK + 2];     // +pad for u32 copies
    __shared__ unsigned short Esm[PBLK];          // 1 KB

    const int tid  = threadIdx.x;
    const int lane = tid & 31;
    const int w    = tid >> 5;                    // owning warp index
    const int cid  = blockIdx.x;
    const float* fbase = feat + (size_t)(cid >> 7) * CC * NN + (cid & 127) * PBLK;

    if (tid < NBUCK + 1) Psm[tid] = g_pref[cid * (NBUCK + 1) + tid];
    if (tid < PBLK / 2)
        ((uint32_t*)Esm)[tid] = ((const uint32_t*)(g_entries + cid * PBLK))[tid];

    float r0[4], r1[4], r2[4], r3[4];
    #pragma unroll
    for (int k = 0; k < 4; ++k) {
        r0[k] = -INFINITY; r1[k] = -INFINITY;
        r2[k] = -INFINITY; r3[k] = -INFINITY;
    }

    const uint32_t tile_u = (uint32_t)__cvta_generic_to_shared(tile);
    auto prefetch = [&](int ht) {
        #pragma unroll
        for (int k = 0; k < 2; ++k) {
            int i  = tid + k * THREADS1;          // 0..1023
            int cr = i >> 3;                      // channel row 0..127
            int gl = i & 7;                       // local granule
            int g  = ((ht & 1) << 3) + gl;        // logical granule 0..15
            uint32_t dst = tile_u +
                (uint32_t)((cr * TCOLS + ((g ^ (cr & 15)) << 2)) * 4);
            cp_async16(dst, fbase + (size_t)cr * NN + ht * HT + gl * 4);
        }
        cp_commit();
    };

    prefetch(0);
    prefetch(1);
    __syncthreads();    // Psm/Esm visible; pipeline primed

    for (int ht = 0; ht < NHT; ++ht) {
        if (ht < NHT - 1) cp_wait<1>(); else cp_wait<0>();
        __syncthreads();

        const int half8 = (ht & 1) << 3;
        const int i0 = Psm[w * NHT + ht];
        const int i1 = Psm[w * NHT + ht + 1];
        for (int i = i0; i < i1; ++i) {           // warp-uniform walk
            const unsigned e  = Esm[i];           // broadcast
            const int pt = e & 511;
            const int sl = e >> 9;                // warp-uniform 0..3
            const int g  = half8 + ((pt & 31) >> 2);
            const int sw0 = ((g ^ (lane & 15)) << 2) + (pt & 3);
            float v0 = tile[(lane     ) * TCOLS + sw0];
            float v1 = tile[(lane + 32) * TCOLS + sw0];
            float v2 = tile[(lane + 64) * TCOLS + sw0];
            float v3 = tile[(lane + 96) * TCOLS + sw0];
            r0[0] = (sl == 0) ? fmaxf(r0[0], v0) : r0[0];
            r0[1] = (sl == 0) ? fmaxf(r0[1], v1) : r0[1];
            r0[2] = (sl == 0) ? fmaxf(r0[2], v2) : r0[2];
            r0[3] = (sl == 0) ? fmaxf(r0[3], v3) : r0[3];
            r1[0] = (sl == 1) ? fmaxf(r1[0], v0) : r1[0];
            r1[1] = (sl == 1) ? fmaxf(r1[1], v1) : r1[1];
            r1[2] = (sl == 1) ? fmaxf(r1[2], v2) : r1[2];
            r1[3] = (sl == 1) ? fmaxf(r1[3], v3) : r1[3];
            r2[0] = (sl == 2) ? fmaxf(r2[0], v0) : r2[0];
            r2[1] = (sl == 2) ? fmaxf(r2[1], v1) : r2[1];
            r2[2] = (sl == 2) ? fmaxf(r2[2], v2) : r2[2];
            r2[3] = (sl == 2) ? fmaxf(r2[3], v3) : r2[3];
            r3[0] = (sl == 3) ? fmaxf(r3[0], v0) : r3[0];
            r3[1] = (sl == 3) ? fmaxf(r3[1], v1) : r3[1];
            r3[2] = (sl == 3) ? fmaxf(r3[2], v2) : r3[2];
            r3[3] = (sl == 3) ? fmaxf(r3[3], v3) : r3[3];
        }
        __syncthreads();                          // buffer reads complete
        if (ht + 2 < NHT) prefetch(ht + 2);
    }

    // Writeout: 128B-coalesced per (seg, k-group) row segment.
    float* outp = g_partial + (size_t)cid * (NOBJ * CC) + (4 * w) * CC + lane;
    #pragma unroll
    for (int k = 0; k < 4; ++k) {
        outp[0 * CC + 32 * k] = r0[k];
        outp[1 * CC + 32 * k] = r1[k];
        outp[2 * CC + 32 * k] = r2[k];
        outp[3 * CC + 32 * k] = r3[k];
    }
}

// ---------------------------------------------------------------------------
// Stage 2: reduce 128 per-chunk partials per (b, seg, c-quad); -inf -> 0.
// ---------------------------------------------------------------------------
__global__ void seg_max_stage2(float* __restrict__ out) {
    int o4 = blockIdx.x * blockDim.x + threadIdx.x;   // 0..16383 float4s
    int c4 = o4 & (CC / 4 - 1);
    int g  = o4 >> 5;
    int b  = g >> 6;
    int s  = g & (NOBJ - 1);

    const float4* __restrict__ p =
        (const float4*)(g_partial + (size_t)b * NCHUNK * (NOBJ * CC) + s * CC) + c4;

    float4 m = make_float4(-INFINITY, -INFINITY, -INFINITY, -INFINITY);
    #pragma unroll 4
    for (int k = 0; k < NCHUNK; ++k) {
        float4 v = p[(size_t)k * (NOBJ * CC / 4)];
        m.x = fmaxf(m.x, v.x); m.y = fmaxf(m.y, v.y);
        m.z = fmaxf(m.z, v.z); m.w = fmaxf(m.w, v.w);
    }
    float4 r;
    r.x = isfinite(m.x) ? m.x : 0.0f;
    r.y = isfinite(m.y) ? m.y : 0.0f;
    r.z = isfinite(m.z) ? m.z : 0.0f;
    r.w = isfinite(m.w) ? m.w : 0.0f;
    ((float4*)out)[o4] = r;
}

// ---------------------------------------------------------------------------
extern "C" void kernel_launch(void* const* d_in, const int* in_sizes, int n_in,
                              void* d_out, int out_size)
{
    const float* feat = nullptr;
    const int*   idx  = nullptr;
    for (int i = 0; i < n_in; ++i) {
        if (in_sizes[i] == BB * CC * NN)  feat = (const float*)d_in[i];
        else if (in_sizes[i] == BB * NN)  idx  = (const int*)d_in[i];
    }

    prep_sort<<<NCID, 256>>>(idx);
    seg_max_stage1<<<NCID, THREADS1>>>(feat);
    seg_max_stage2<<<(BB * NOBJ * CC / 4) / 256, 256>>>((float*)d_out);
}